// round 3
// baseline (speedup 1.0000x reference)
#include <cuda_runtime.h>
#include <math.h>

#define HWSZ 65536
#define IMW  256
#define NKPT 68

// Per-batch similarity transform: 9 floats sR (row-major) + 3 floats t.
__device__ float g_sRt[64 * 12];

// ---------------------------------------------------------------------------
// Kernel 1: per-batch Umeyama fit on 68 keypoints.
// One block per batch. Threads 0..67 gather the keypoint values; thread 0
// then solves the 3x3 problem serially in double precision (negligible cost
// at 64-way block parallelism; Jacobi on 3x3 converges in <10 sweeps).
// ---------------------------------------------------------------------------
__global__ void fit_kernel(const float* __restrict__ Offset,
                           const float* __restrict__ Pos,
                           const float* __restrict__ meanp,
                           const int*   __restrict__ uv) {
    int b = blockIdx.x;
    int k = threadIdx.x;
    __shared__ float s_src[NKPT][3];
    __shared__ float s_dst[NKPT][3];

    if (k < NKPT) {
        int p = uv[2 * k] * IMW + uv[2 * k + 1];
        const float* ob = Offset + (size_t)b * 3 * HWSZ;
        const float* pb = Pos    + (size_t)b * 3 * HWSZ;
        // offsetmap = (Offset*4 + mean) * REVERT([1,-1,1])
        s_src[k][0] =  fmaf(ob[p],            4.f, meanp[p]);
        s_src[k][1] = -fmaf(ob[HWSZ + p],     4.f, meanp[HWSZ + p]);
        s_src[k][2] =  fmaf(ob[2 * HWSZ + p], 4.f, meanp[2 * HWSZ + p]);
        s_dst[k][0] = pb[p];
        s_dst[k][1] = pb[HWSZ + p];
        s_dst[k][2] = pb[2 * HWSZ + p];
    }
    __syncthreads();
    if (k != 0) return;

    // Means
    double mus[3] = {0, 0, 0}, mud[3] = {0, 0, 0};
    for (int i = 0; i < NKPT; i++)
        for (int c = 0; c < 3; c++) { mus[c] += s_src[i][c]; mud[c] += s_dst[i][c]; }
    const double inv_n = 1.0 / NKPT;
    for (int c = 0; c < 3; c++) { mus[c] *= inv_n; mud[c] *= inv_n; }

    // Covariance A = dd^T sd / n, and var_s
    double A[3][3] = {{0,0,0},{0,0,0},{0,0,0}};
    double var_s = 0.0;
    for (int i = 0; i < NKPT; i++) {
        double sd[3], dd[3];
        for (int c = 0; c < 3; c++) {
            sd[c] = (double)s_src[i][c] - mus[c];
            dd[c] = (double)s_dst[i][c] - mud[c];
            var_s += sd[c] * sd[c];
        }
        for (int r = 0; r < 3; r++)
            for (int c = 0; c < 3; c++) A[r][c] += dd[r] * sd[c];
    }
    for (int r = 0; r < 3; r++)
        for (int c = 0; c < 3; c++) A[r][c] *= inv_n;
    var_s *= inv_n;

    double det = A[0][0] * (A[1][1] * A[2][2] - A[1][2] * A[2][1])
               - A[0][1] * (A[1][0] * A[2][2] - A[1][2] * A[2][0])
               + A[0][2] * (A[1][0] * A[2][1] - A[1][1] * A[2][0]);

    // Bm = A^T A (symmetric PSD), eigendecompose via cyclic Jacobi.
    double Bm[3][3];
    for (int r = 0; r < 3; r++)
        for (int c = 0; c < 3; c++) {
            double s = 0;
            for (int m = 0; m < 3; m++) s += A[m][r] * A[m][c];
            Bm[r][c] = s;
        }
    double V[3][3] = {{1,0,0},{0,1,0},{0,0,1}};
    for (int sweep = 0; sweep < 15; sweep++) {
        double off = fabs(Bm[0][1]) + fabs(Bm[0][2]) + fabs(Bm[1][2]);
        if (off < 1e-30) break;
        for (int p = 0; p < 2; p++)
            for (int q = p + 1; q < 3; q++) {
                double bpq = Bm[p][q];
                if (fabs(bpq) < 1e-300) continue;
                double theta = (Bm[q][q] - Bm[p][p]) / (2.0 * bpq);
                double tt = ((theta >= 0.0) ? 1.0 : -1.0) /
                            (fabs(theta) + sqrt(theta * theta + 1.0));
                double c = 1.0 / sqrt(tt * tt + 1.0);
                double s = tt * c;
                for (int i = 0; i < 3; i++) {
                    double bip = Bm[i][p], biq = Bm[i][q];
                    Bm[i][p] = c * bip - s * biq;
                    Bm[i][q] = s * bip + c * biq;
                }
                for (int i = 0; i < 3; i++) {
                    double bpi = Bm[p][i], bqi = Bm[q][i];
                    Bm[p][i] = c * bpi - s * bqi;
                    Bm[q][i] = s * bpi + c * bqi;
                }
                for (int i = 0; i < 3; i++) {
                    double vip = V[i][p], viq = V[i][q];
                    V[i][p] = c * vip - s * viq;
                    V[i][q] = s * vip + c * viq;
                }
            }
    }

    // Sort eigenpairs descending -> singular values S of A
    double eig[3] = {Bm[0][0], Bm[1][1], Bm[2][2]};
    int ord[3] = {0, 1, 2};
    for (int i = 0; i < 2; i++)
        for (int j = i + 1; j < 3; j++)
            if (eig[ord[j]] > eig[ord[i]]) { int t = ord[i]; ord[i] = ord[j]; ord[j] = t; }
    double S[3], Vc[3][3];
    for (int j = 0; j < 3; j++) {
        double e = eig[ord[j]];
        S[j] = (e > 0.0) ? sqrt(e) : 0.0;
        for (int r = 0; r < 3; r++) Vc[r][j] = V[r][ord[j]];
    }

    double d2 = (det < 0.0) ? -1.0 : 1.0;
    double dv[3] = {1.0, 1.0, d2};
    double scale = (S[0] + S[1] + d2 * S[2]) / var_s;

    // sR = scale * U diag(dv) V^T = scale * A * (V diag(dv/S) V^T)
    double M[3][3];
    for (int r = 0; r < 3; r++)
        for (int c = 0; c < 3; c++) {
            double s = 0;
            for (int j = 0; j < 3; j++) s += Vc[r][j] * (dv[j] / S[j]) * Vc[c][j];
            M[r][c] = s;
        }
    double sR[3][3];
    for (int r = 0; r < 3; r++)
        for (int c = 0; c < 3; c++) {
            double s = 0;
            for (int m = 0; m < 3; m++) s += A[r][m] * M[m][c];
            sR[r][c] = scale * s;
        }

    float* outp = &g_sRt[b * 12];
    for (int r = 0; r < 3; r++)
        for (int c = 0; c < 3; c++) outp[r * 3 + c] = (float)sR[r][c];
    for (int r = 0; r < 3; r++) {
        double tr = mud[r] - (sR[r][0] * mus[0] + sR[r][1] * mus[1] + sR[r][2] * mus[2]);
        outp[9 + r] = (float)tr;
    }
}

// ---------------------------------------------------------------------------
// Kernel 2: streaming transform. float4-vectorized; HBM-bound.
// out[b,d,p] = sum_c sR[b,d,c] * off_c(p) + t[b,d]
// off = (Offset*4 + mean) * [1,-1,1]
// ---------------------------------------------------------------------------
__global__ __launch_bounds__(256) void apply_kernel(
        const float* __restrict__ Offset,
        const float* __restrict__ meanp,
        float* __restrict__ out) {
    int b = blockIdx.y;
    int idx = blockIdx.x * 256 + threadIdx.x;  // float4 index within HW plane

    __shared__ float sr[12];
    if (threadIdx.x < 12) sr[threadIdx.x] = g_sRt[b * 12 + threadIdx.x];
    __syncthreads();

    const float r00 = sr[0], r01 = sr[1], r02 = sr[2];
    const float r10 = sr[3], r11 = sr[4], r12 = sr[5];
    const float r20 = sr[6], r21 = sr[7], r22 = sr[8];
    const float t0 = sr[9], t1 = sr[10], t2 = sr[11];

    size_t base = (size_t)b * 3 * HWSZ;
    const float4* ib = (const float4*)(Offset + base);
    const float4* mb = (const float4*)meanp;
    float4* ob = (float4*)(out + base);

    float4 x  = ib[idx];
    float4 y  = ib[HWSZ / 4 + idx];
    float4 z  = ib[HWSZ / 2 + idx];
    float4 m0 = mb[idx];
    float4 m1 = mb[HWSZ / 4 + idx];
    float4 m2 = mb[HWSZ / 2 + idx];

    float xa[4] = {x.x, x.y, x.z, x.w};
    float ya[4] = {y.x, y.y, y.z, y.w};
    float za[4] = {z.x, z.y, z.z, z.w};
    float ma0[4] = {m0.x, m0.y, m0.z, m0.w};
    float ma1[4] = {m1.x, m1.y, m1.z, m1.w};
    float ma2[4] = {m2.x, m2.y, m2.z, m2.w};
    float o0[4], o1[4], o2[4];

#pragma unroll
    for (int i = 0; i < 4; i++) {
        float c0 =  fmaf(xa[i], 4.f, ma0[i]);
        float c1 = -fmaf(ya[i], 4.f, ma1[i]);
        float c2 =  fmaf(za[i], 4.f, ma2[i]);
        o0[i] = fmaf(r00, c0, fmaf(r01, c1, fmaf(r02, c2, t0)));
        o1[i] = fmaf(r10, c0, fmaf(r11, c1, fmaf(r12, c2, t1)));
        o2[i] = fmaf(r20, c0, fmaf(r21, c1, fmaf(r22, c2, t2)));
    }

    ob[idx]            = make_float4(o0[0], o0[1], o0[2], o0[3]);
    ob[HWSZ / 4 + idx] = make_float4(o1[0], o1[1], o1[2], o1[3]);
    ob[HWSZ / 2 + idx] = make_float4(o2[0], o2[1], o2[2], o2[3]);
}

extern "C" void kernel_launch(void* const* d_in, const int* in_sizes, int n_in,
                              void* d_out, int out_size) {
    const float* Offset = (const float*)d_in[0];
    const float* Pos    = (const float*)d_in[1];
    const float* meanp  = (const float*)d_in[2];
    const int*   uv     = (const int*)d_in[3];
    float* out = (float*)d_out;

    int B = in_sizes[0] / (3 * HWSZ);

    fit_kernel<<<B, 128>>>(Offset, Pos, meanp, uv);

    dim3 grid(HWSZ / (4 * 256), B);
    apply_kernel<<<grid, 256>>>(Offset, meanp, out);
}

// round 16
// speedup vs baseline: 6.2696x; 6.2696x over previous
#include <cuda_runtime.h>
#include <math.h>

#define HWSZ 65536
#define IMW  256
#define NKPT 68

// Per-batch similarity transform: 9 floats sR (row-major) + 3 floats t.
__device__ float g_sRt[64 * 12];

// ---------------------------------------------------------------------------
// Kernel 1: per-batch Umeyama fit on 68 keypoints — ALL FP32.
// One block per batch. Threads 0..67 gather; thread 0 solves the 3x3 problem
// serially in float (MUFU rsqrt/div, capped Jacobi). FP64 version measured
// ~130us due to software double sqrt/div chains; fp32 needs only ~1e-4 acc.
// ---------------------------------------------------------------------------
__global__ void fit_kernel(const float* __restrict__ Offset,
                           const float* __restrict__ Pos,
                           const float* __restrict__ meanp,
                           const int*   __restrict__ uv) {
    int b = blockIdx.x;
    int k = threadIdx.x;
    __shared__ float s_src[NKPT][3];
    __shared__ float s_dst[NKPT][3];

    if (k < NKPT) {
        int p = uv[2 * k] * IMW + uv[2 * k + 1];
        const float* ob = Offset + (size_t)b * 3 * HWSZ;
        const float* pb = Pos    + (size_t)b * 3 * HWSZ;
        // offsetmap = (Offset*4 + mean) * REVERT([1,-1,1])
        s_src[k][0] =  fmaf(ob[p],            4.f, meanp[p]);
        s_src[k][1] = -fmaf(ob[HWSZ + p],     4.f, meanp[HWSZ + p]);
        s_src[k][2] =  fmaf(ob[2 * HWSZ + p], 4.f, meanp[2 * HWSZ + p]);
        s_dst[k][0] = pb[p];
        s_dst[k][1] = pb[HWSZ + p];
        s_dst[k][2] = pb[2 * HWSZ + p];
    }
    __syncthreads();
    if (k != 0) return;

    // Means
    float mus[3] = {0, 0, 0}, mud[3] = {0, 0, 0};
    for (int i = 0; i < NKPT; i++)
        for (int c = 0; c < 3; c++) { mus[c] += s_src[i][c]; mud[c] += s_dst[i][c]; }
    const float inv_n = 1.0f / NKPT;
    for (int c = 0; c < 3; c++) { mus[c] *= inv_n; mud[c] *= inv_n; }

    // Covariance A = dd^T sd / n, and var_s
    float A[3][3] = {{0,0,0},{0,0,0},{0,0,0}};
    float var_s = 0.0f;
    for (int i = 0; i < NKPT; i++) {
        float sd[3], dd[3];
        for (int c = 0; c < 3; c++) {
            sd[c] = s_src[i][c] - mus[c];
            dd[c] = s_dst[i][c] - mud[c];
            var_s = fmaf(sd[c], sd[c], var_s);
        }
        for (int r = 0; r < 3; r++)
            for (int c = 0; c < 3; c++) A[r][c] = fmaf(dd[r], sd[c], A[r][c]);
    }
    for (int r = 0; r < 3; r++)
        for (int c = 0; c < 3; c++) A[r][c] *= inv_n;
    var_s *= inv_n;

    float det = A[0][0] * (A[1][1] * A[2][2] - A[1][2] * A[2][1])
              - A[0][1] * (A[1][0] * A[2][2] - A[1][2] * A[2][0])
              + A[0][2] * (A[1][0] * A[2][1] - A[1][1] * A[2][0]);

    // Bm = A^T A (symmetric PSD), eigendecompose via cyclic Jacobi (fp32).
    float Bm[3][3];
    float normB = 0.0f;
    for (int r = 0; r < 3; r++)
        for (int c = 0; c < 3; c++) {
            float s = 0;
            for (int m = 0; m < 3; m++) s = fmaf(A[m][r], A[m][c], s);
            Bm[r][c] = s;
            normB += fabsf(s);
        }
    float V[3][3] = {{1,0,0},{0,1,0},{0,0,1}};
    const float off_tol = 1e-7f * normB + 1e-30f;
    for (int sweep = 0; sweep < 8; sweep++) {
        float off = fabsf(Bm[0][1]) + fabsf(Bm[0][2]) + fabsf(Bm[1][2]);
        if (off < off_tol) break;
        for (int p = 0; p < 2; p++)
            for (int q = p + 1; q < 3; q++) {
                float bpq = Bm[p][q];
                if (fabsf(bpq) < 1e-30f) continue;
                float theta = (Bm[q][q] - Bm[p][p]) / (2.0f * bpq);
                float tt = ((theta >= 0.0f) ? 1.0f : -1.0f) /
                           (fabsf(theta) + sqrtf(fmaf(theta, theta, 1.0f)));
                float c = rsqrtf(fmaf(tt, tt, 1.0f));
                float s = tt * c;
                for (int i = 0; i < 3; i++) {
                    float bip = Bm[i][p], biq = Bm[i][q];
                    Bm[i][p] = c * bip - s * biq;
                    Bm[i][q] = s * bip + c * biq;
                }
                for (int i = 0; i < 3; i++) {
                    float bpi = Bm[p][i], bqi = Bm[q][i];
                    Bm[p][i] = c * bpi - s * bqi;
                    Bm[q][i] = s * bpi + c * bqi;
                }
                for (int i = 0; i < 3; i++) {
                    float vip = V[i][p], viq = V[i][q];
                    V[i][p] = c * vip - s * viq;
                    V[i][q] = s * vip + c * viq;
                }
            }
    }

    // Sort eigenpairs descending -> singular values S of A
    float eig[3] = {Bm[0][0], Bm[1][1], Bm[2][2]};
    int ord[3] = {0, 1, 2};
    for (int i = 0; i < 2; i++)
        for (int j = i + 1; j < 3; j++)
            if (eig[ord[j]] > eig[ord[i]]) { int t = ord[i]; ord[i] = ord[j]; ord[j] = t; }
    float S[3], Vc[3][3];
    for (int j = 0; j < 3; j++) {
        float e = eig[ord[j]];
        S[j] = (e > 0.0f) ? sqrtf(e) : 0.0f;
        for (int r = 0; r < 3; r++) Vc[r][j] = V[r][ord[j]];
    }

    float d2 = (det < 0.0f) ? -1.0f : 1.0f;
    float dv[3] = {1.0f, 1.0f, d2};
    float scale = (S[0] + S[1] + d2 * S[2]) / var_s;

    // sR = scale * U diag(dv) V^T = scale * A * (V diag(dv/S) V^T)
    float M[3][3];
    float invS[3];
    for (int j = 0; j < 3; j++) invS[j] = dv[j] / S[j];
    for (int r = 0; r < 3; r++)
        for (int c = 0; c < 3; c++) {
            float s = 0;
            for (int j = 0; j < 3; j++) s = fmaf(Vc[r][j] * invS[j], Vc[c][j], s);
            M[r][c] = s;
        }
    float sR[3][3];
    for (int r = 0; r < 3; r++)
        for (int c = 0; c < 3; c++) {
            float s = 0;
            for (int m = 0; m < 3; m++) s = fmaf(A[r][m], M[m][c], s);
            sR[r][c] = scale * s;
        }

    float* outp = &g_sRt[b * 12];
    for (int r = 0; r < 3; r++)
        for (int c = 0; c < 3; c++) outp[r * 3 + c] = sR[r][c];
    for (int r = 0; r < 3; r++)
        outp[9 + r] = mud[r] - (sR[r][0] * mus[0] + sR[r][1] * mus[1] + sR[r][2] * mus[2]);
}

// ---------------------------------------------------------------------------
// Kernel 2: streaming transform. float4-vectorized, 2 chunks per thread for
// higher MLP (prev: DRAM 48%, occ 64%, issue 20% -> latency-limited).
// out[b,d,p] = sum_c sR[b,d,c] * off_c(p) + t[b,d],  off = (Offset*4+mean)*[1,-1,1]
// ---------------------------------------------------------------------------
#define IPT 2
__global__ __launch_bounds__(256) void apply_kernel(
        const float* __restrict__ Offset,
        const float* __restrict__ meanp,
        float* __restrict__ out) {
    int b = blockIdx.y;
    int base4 = blockIdx.x * (256 * IPT) + threadIdx.x;  // float4 index in HW plane

    __shared__ float sr[12];
    if (threadIdx.x < 12) sr[threadIdx.x] = g_sRt[b * 12 + threadIdx.x];
    __syncthreads();

    const float r00 = sr[0], r01 = sr[1], r02 = sr[2];
    const float r10 = sr[3], r11 = sr[4], r12 = sr[5];
    const float r20 = sr[6], r21 = sr[7], r22 = sr[8];
    const float t0 = sr[9], t1 = sr[10], t2 = sr[11];

    size_t base = (size_t)b * 3 * HWSZ;
    const float4* ib = (const float4*)(Offset + base);
    const float4* mb = (const float4*)meanp;
    float4* ob = (float4*)(out + base);

    float4 X[IPT], Y[IPT], Z[IPT], M0[IPT], M1[IPT], M2[IPT];
#pragma unroll
    for (int j = 0; j < IPT; j++) {
        int idx = base4 + j * 256;
        X[j]  = ib[idx];
        Y[j]  = ib[HWSZ / 4 + idx];
        Z[j]  = ib[HWSZ / 2 + idx];
        M0[j] = mb[idx];
        M1[j] = mb[HWSZ / 4 + idx];
        M2[j] = mb[HWSZ / 2 + idx];
    }

#pragma unroll
    for (int j = 0; j < IPT; j++) {
        int idx = base4 + j * 256;
        float xa[4]  = {X[j].x, X[j].y, X[j].z, X[j].w};
        float ya[4]  = {Y[j].x, Y[j].y, Y[j].z, Y[j].w};
        float za[4]  = {Z[j].x, Z[j].y, Z[j].z, Z[j].w};
        float ma0[4] = {M0[j].x, M0[j].y, M0[j].z, M0[j].w};
        float ma1[4] = {M1[j].x, M1[j].y, M1[j].z, M1[j].w};
        float ma2[4] = {M2[j].x, M2[j].y, M2[j].z, M2[j].w};
        float o0[4], o1[4], o2[4];
#pragma unroll
        for (int i = 0; i < 4; i++) {
            float c0 =  fmaf(xa[i], 4.f, ma0[i]);
            float c1 = -fmaf(ya[i], 4.f, ma1[i]);
            float c2 =  fmaf(za[i], 4.f, ma2[i]);
            o0[i] = fmaf(r00, c0, fmaf(r01, c1, fmaf(r02, c2, t0)));
            o1[i] = fmaf(r10, c0, fmaf(r11, c1, fmaf(r12, c2, t1)));
            o2[i] = fmaf(r20, c0, fmaf(r21, c1, fmaf(r22, c2, t2)));
        }
        ob[idx]            = make_float4(o0[0], o0[1], o0[2], o0[3]);
        ob[HWSZ / 4 + idx] = make_float4(o1[0], o1[1], o1[2], o1[3]);
        ob[HWSZ / 2 + idx] = make_float4(o2[0], o2[1], o2[2], o2[3]);
    }
}

extern "C" void kernel_launch(void* const* d_in, const int* in_sizes, int n_in,
                              void* d_out, int out_size) {
    const float* Offset = (const float*)d_in[0];
    const float* Pos    = (const float*)d_in[1];
    const float* meanp  = (const float*)d_in[2];
    const int*   uv     = (const int*)d_in[3];
    float* out = (float*)d_out;

    int B = in_sizes[0] / (3 * HWSZ);

    fit_kernel<<<B, 128>>>(Offset, Pos, meanp, uv);

    dim3 grid(HWSZ / (4 * 256 * IPT), B);
    apply_kernel<<<grid, 256>>>(Offset, meanp, out);
}